// round 16
// baseline (speedup 1.0000x reference)
#include <cuda_runtime.h>
#include <cuda_fp16.h>
#include <stdint.h>

#define NN 50000
#define EE 1600000
#define YS1 4224          // padded y stride (halves) for 64->64 layers (33*128)
#define YS3 256           // y stride for layer3
#define NPAD 4224         // packed-weight column pad (layers 1/2)
#define SCAN_B 49         // ceil(50000/1024)

// ---------------- device scratch (no runtime allocation allowed) ------------
__device__ __align__(16) __half g_y[(size_t)NN * YS1];   // 422 MB
__device__ __align__(16) __half g_wc1[64 * NPAD];
__device__ __align__(16) __half g_wc2[64 * NPAD];
__device__ __align__(16) __half g_wc3[64 * 256];
__device__ __align__(16) __half g_ah[NN * 64];           // relu(ans) fp16 (GEMM A)
__device__ __align__(16) float  g_ansF[NN * 64];         // layer1 out fp32 (residual)
__device__ __align__(16) __half g_m0[(size_t)NN * 320];  // layer0 moments + x, fp16
__device__ __align__(16) __half g_wb0[320 * 64];         // layer0 packed weights
__device__ float  g_bias0[64];
__device__ float  g_bias1[64];
__device__ float  g_bias2[64];
__device__ int    g_cnt[NN + 1];
__device__ int    g_rowp[NN + 1];
__device__ int    g_rank[EE];
__device__ int    g_bsum[SCAN_B];
__device__ int    g_boff[SCAN_B + 1];
// edge record: .x = j | kb<<20 | m<<31 ; .y/.z/.w = w0,w1,w2 (fp32 bits)
__device__ __align__(16) uint4 g_ed[EE];

// ---------------- mma / async helpers ----------------------------------------
__device__ __forceinline__ void ldsm4(uint32_t& r0, uint32_t& r1, uint32_t& r2,
                                      uint32_t& r3, uint32_t addr) {
    asm volatile("ldmatrix.sync.aligned.m8n8.x4.shared.b16 {%0,%1,%2,%3}, [%4];"
                 : "=r"(r0), "=r"(r1), "=r"(r2), "=r"(r3) : "r"(addr));
}
__device__ __forceinline__ void ldsm4t(uint32_t& r0, uint32_t& r1, uint32_t& r2,
                                       uint32_t& r3, uint32_t addr) {
    asm volatile("ldmatrix.sync.aligned.m8n8.x4.trans.shared.b16 {%0,%1,%2,%3}, [%4];"
                 : "=r"(r0), "=r"(r1), "=r"(r2), "=r"(r3) : "r"(addr));
}
__device__ __forceinline__ void mma16816(float* c, const uint32_t* a,
                                         uint32_t b0, uint32_t b1) {
    asm volatile(
        "mma.sync.aligned.m16n8k16.row.col.f32.f16.f16.f32 "
        "{%0,%1,%2,%3}, {%4,%5,%6,%7}, {%8,%9}, {%0,%1,%2,%3};"
        : "+f"(c[0]), "+f"(c[1]), "+f"(c[2]), "+f"(c[3])
        : "r"(a[0]), "r"(a[1]), "r"(a[2]), "r"(a[3]), "r"(b0), "r"(b1));
}
__device__ __forceinline__ void cpa16(uint32_t dst, const void* src) {
    asm volatile("cp.async.cg.shared.global [%0], [%1], 16;" :: "r"(dst), "l"(src));
}
__device__ __forceinline__ void cpa16z(uint32_t dst, const void* src, int nbytes) {
    asm volatile("cp.async.cg.shared.global [%0], [%1], 16, %2;"
                 :: "r"(dst), "l"(src), "r"(nbytes));
}
#define CP_COMMIT() asm volatile("cp.async.commit_group;")
#define CP_WAIT0()  asm volatile("cp.async.wait_group 0;")

// ---------------- fused weight pack + hist (after cnt zero) ------------------
#define R0 (320 * 64)
#define R1 (64 * NPAD)
#define R3 (64 * 256)
#define PACK_W (R0 + 2 * R1 + R3)
#define PACK_BLK ((PACK_W + 255) / 256)
#define HIST_BLK ((EE + 255) / 256)

__device__ __forceinline__ float wcat_val(const float* CW, const float* FW,
                                          int k, int col, int ncols,
                                          int coutShift, int coutMask) {
    if (col >= ncols) return 0.f;
    int cout = 1 << coutShift;
    int kcoutTot = 64 << coutShift;
    if (col < kcoutTot) {
        int kk = col >> coutShift;
        int co = col & coutMask;
        return __ldg(CW + (size_t)(kk * 64 + k) * cout + co);
    }
    return __ldg(FW + (size_t)k * cout + (col - kcoutTot));
}

__global__ void zero_cnt_kernel() {
    int t = blockIdx.x * blockDim.x + threadIdx.x;
    if (t <= NN) g_cnt[t] = 0;
}

__global__ void packHist_kernel(
    const float* __restrict__ cw0, const float* __restrict__ fw0,
    const float* __restrict__ cb0, const float* __restrict__ fb0,
    const float* __restrict__ cw1, const float* __restrict__ fw1,
    const float* __restrict__ cb1, const float* __restrict__ fb1,
    const float* __restrict__ cw2, const float* __restrict__ fw2,
    const float* __restrict__ cb2, const float* __restrict__ fb2,
    const float* __restrict__ cw3, const float* __restrict__ fw3,
    const int* __restrict__ ei, int E) {
    if (blockIdx.x >= PACK_BLK) {
        int e = (blockIdx.x - PACK_BLK) * blockDim.x + threadIdx.x;
        if (e < E) g_rank[e] = atomicAdd(&g_cnt[__ldg(ei + e)], 1);
        return;
    }
    int idx = blockIdx.x * blockDim.x + threadIdx.x;
    if (idx >= PACK_W) return;
    if (idx < R0) {
        int row = idx >> 6, co = idx & 63;
        float v = 0.f;
        if (row < 256) {
            int kb = row >> 2, c = row & 3;
            if (co >= 32) v = __ldg(cw0 + (size_t)(kb * 4 + c) * 32 + (co - 32));
        } else if (row < 260) {
            int c = row - 256;
            if (co < 32) v = __ldg(fw0 + (size_t)c * 32 + co);
        }
        g_wb0[idx] = __float2half(v);
        if (idx < 64)
            g_bias0[idx] = (idx < 32) ? __ldg(fb0 + idx) : __ldg(cb0 + idx - 32);
        return;
    }
    idx -= R0;
    if (idx < R1) {
        int k = idx / NPAD, col = idx - k * NPAD;
        g_wc1[idx] = __float2half(wcat_val(cw1, fw1, k, col, 4160, 6, 63));
        if (idx < 64) g_bias1[idx] = __ldg(cb1 + idx) + __ldg(fb1 + idx);
        return;
    }
    idx -= R1;
    if (idx < R1) {
        int k = idx / NPAD, col = idx - k * NPAD;
        g_wc2[idx] = __float2half(wcat_val(cw2, fw2, k, col, 4160, 6, 63));
        if (idx < 64) g_bias2[idx] = __ldg(cb2 + idx) + __ldg(fb2 + idx);
        return;
    }
    idx -= R1;
    int k = idx >> 8, col = idx & 255;
    g_wc3[idx] = __float2half(wcat_val(cw3, fw3, k, col, 130, 1, 1));
}

// ---------------- scans ------------------------------------------------------
// full local exclusive scan -> g_rowp (pre-offset); block total -> g_bsum
__global__ void scan1_kernel() {
    __shared__ int sh[1024];
    int b = blockIdx.x, tid = threadIdx.x;
    int idx = b * 1024 + tid;
    int v = (idx < NN) ? g_cnt[idx] : 0;
    int orig = v;
    sh[tid] = v;
    __syncthreads();
    for (int off = 1; off < 1024; off <<= 1) {
        int t = (tid >= off) ? sh[tid - off] : 0;
        __syncthreads();
        sh[tid] += t;
        __syncthreads();
    }
    if (idx < NN) g_rowp[idx] = sh[tid] - orig;
    if (tid == 1023) g_bsum[b] = sh[1023];
}

__global__ void scan2_kernel() {
    __shared__ int sh[64];
    int tid = threadIdx.x;
    int v = (tid < SCAN_B) ? g_bsum[tid] : 0;
    sh[tid] = v;
    __syncthreads();
    for (int off = 1; off < 64; off <<= 1) {
        int t = (tid >= off) ? sh[tid - off] : 0;
        __syncthreads();
        sh[tid] += t;
        __syncthreads();
    }
    if (tid < SCAN_B) g_boff[tid] = sh[tid] - v;
    if (tid == SCAN_B - 1) g_boff[SCAN_B] = sh[tid];
}

// add block offset (trivial elementwise pass)
__global__ void scan3_kernel() {
    int b = blockIdx.x, tid = threadIdx.x;
    int idx = b * 1024 + tid;
    if (idx < NN) g_rowp[idx] += g_boff[b];
    if (b == 0 && tid == 0) g_rowp[NN] = g_boff[SCAN_B];
}

__global__ void scatter_kernel(const float* __restrict__ pos,
                               const int* __restrict__ ei,
                               const int* __restrict__ ej, int E) {
    int e = blockIdx.x * blockDim.x + threadIdx.x;
    if (e >= E) return;
    int i = __ldg(ei + e), j = __ldg(ej + e);
    const float2* p2 = (const float2*)pos;
    float2 pi = __ldg(p2 + i);
    float2 pj = __ldg(p2 + j);
    float dx = pi.x - pj.x;
    float dy = pi.y - pj.y;
    dx = fminf(1.f, fmaxf(-1.f, dx));
    dy = fminf(1.f, fmaxf(-1.f, dy));
    uint32_t m = (i != j) ? 1u : 0u;
    float mf = (float)m;
    float r = sqrtf(dx * dx + dy * dy + 1e-12f);
    float u = fminf(1.f, fmaxf(-1.f, 2.f * r - 1.f));
    float v = atan2f(dy, dx) * 0.318309886183790672f;   // 1/pi
    float su = (u + 1.f) * 3.5f;
    int   iu = min(6, (int)floorf(su));
    float tu = su - (float)iu;
    float sv = (v + 1.f) * 3.5f;
    int   iv = min(6, (int)floorf(sv));
    float tv = sv - (float)iv;
    float w0 = (1.f - tu) * (1.f - tv) * mf;
    float w1 = (1.f - tu) * tv * mf;
    float w2 = tu * (1.f - tv) * mf;
    uint32_t kb = (uint32_t)(iu * 8 + iv);
    int p = g_rowp[i] + g_rank[e];
    uint4 ed;
    ed.x = (uint32_t)j | (kb << 20) | (m << 31);
    ed.y = __float_as_uint(w0);
    ed.z = __float_as_uint(w1);
    ed.w = __float_as_uint(w2);
    g_ed[p] = ed;
}

// ---------------- layer 0: moment accumulation (dual-edge, Cin=4) -----------
__global__ void mom0_kernel(const float* __restrict__ X) {
    __shared__ float M0s[8 * 512];
    int warp = threadIdx.x >> 5, lane = threadIdx.x & 31;
    int node = blockIdx.x * 8 + warp;
    float* M = M0s + warp * 512;
    #pragma unroll
    for (int r = 0; r < 16; r++) M[r * 32 + lane] = 0.f;
    __syncwarp();
    if (node < NN) {
        int e0 = g_rowp[node], e1 = g_rowp[node + 1];
        int p = lane >> 4;                 // edge parity
        int t = (lane >> 2) & 3;           // tap
        int c = lane & 3;                  // channel
        int kadd = (t & 1) + ((t >> 1) << 3);
        float* Mp = M + p * 256;
        for (int e = e0; e < e1; e += 2) {
            int ee = e + p;
            if (ee < e1) {
                uint4 ed = __ldg(&g_ed[ee]);
                uint32_t jk = ed.x;
                int j = jk & 0xFFFFF;
                int kb = (jk >> 20) & 63;
                float w0 = __uint_as_float(ed.y);
                float w1 = __uint_as_float(ed.z);
                float w2 = __uint_as_float(ed.w);
                float w3 = (float)(jk >> 31) - w0 - w1 - w2;
                float4 xv = __ldg((const float4*)X + j);
                float wt = (t == 0) ? w0 : (t == 1) ? w1 : (t == 2) ? w2 : w3;
                float xc = (c == 0) ? xv.x : (c == 1) ? xv.y : (c == 2) ? xv.z : xv.w;
                Mp[(kb + kadd) * 4 + c] += wt * xc;
            }
        }
        __syncwarp();
        __half* dst = g_m0 + (size_t)node * 320;
        #pragma unroll
        for (int r = 0; r < 4; r++) {
            int idx = r * 64 + 2 * lane;
            float v0 = M[idx] + M[256 + idx];
            float v1 = M[idx + 1] + M[256 + idx + 1];
            *(__half2*)(dst + idx) = __floats2half2_rn(v0, v1);
        }
        float4 xi = __ldg((const float4*)X + node);
        __half2 hv;
        if (lane == 0)      hv = __floats2half2_rn(xi.x, xi.y);
        else if (lane == 1) hv = __floats2half2_rn(xi.z, xi.w);
        else                hv = __floats2half2_rn(0.f, 0.f);
        *(__half2*)(dst + 256 + 2 * lane) = hv;
    }
}

// ---------------- layer 0 GEMM: ans0 = [M0|x] @ Wb0, bias, relu -> g_ah -----
#define GAST 72
#define SMEMA ((2 * 128 * GAST + 320 * GAST) * 2)   // 82944 B

__global__ void __launch_bounds__(256)
gemmA_kernel() {
    extern __shared__ __half smA[];
    __half* Ab0 = smA;
    __half* Ab1 = smA + 128 * GAST;
    __half* Bs = smA + 2 * 128 * GAST;   // [320][GAST]
    int m0 = blockIdx.x * 128;
    int tid = threadIdx.x;

    #pragma unroll
    for (int it = 0; it < 10; it++) {
        int idx = tid + it * 256;
        int row = idx >> 3;
        int c8 = idx & 7;
        uint4 v = __ldg((const uint4*)(g_wb0 + row * 64 + c8 * 8));
        *(uint4*)(Bs + row * GAST + c8 * 8) = v;
    }

    auto loadA = [&](__half* dst, int kc) {
        uint32_t ab = (uint32_t)__cvta_generic_to_shared(dst);
        #pragma unroll
        for (int it = 0; it < 4; it++) {
            int idx = tid + it * 256;
            int row = idx >> 3;
            int c8 = idx & 7;
            int nb = (m0 + row < NN) ? 16 : 0;
            cpa16z(ab + (row * GAST + c8 * 8) * 2,
                   g_m0 + (size_t)(m0 + row) * 320 + kc * 64 + c8 * 8, nb);
        }
        CP_COMMIT();
    };

    int warp = tid >> 5, lane = tid & 31;
    int wm = warp & 3, wn = warp >> 2;
    uint32_t bsB = (uint32_t)__cvta_generic_to_shared(Bs);

    float c[2][4][4];
    #pragma unroll
    for (int mi = 0; mi < 2; mi++)
        #pragma unroll
        for (int ni = 0; ni < 4; ni++)
            #pragma unroll
            for (int p = 0; p < 4; p++) c[mi][ni][p] = 0.f;

    loadA(Ab0, 0);
    for (int kc = 0; kc < 5; kc++) {
        CP_WAIT0();
        __syncthreads();
        if (kc < 4) loadA((kc & 1) ? Ab0 : Ab1, kc + 1);
        uint32_t asB = (uint32_t)__cvta_generic_to_shared((kc & 1) ? Ab1 : Ab0);
        #pragma unroll
        for (int ks = 0; ks < 4; ks++) {
            int k0 = ks * 16;
            uint32_t a[2][4];
            #pragma unroll
            for (int mi = 0; mi < 2; mi++) {
                int row = wm * 32 + mi * 16 + (lane & 15);
                int col = k0 + ((lane >> 4) << 3);
                ldsm4(a[mi][0], a[mi][1], a[mi][2], a[mi][3],
                      asB + (row * GAST + col) * 2);
            }
            int brow = kc * 64 + k0 + (lane & 15);
            #pragma unroll
            for (int nq = 0; nq < 2; nq++) {
                int bcol = wn * 32 + nq * 16 + ((lane >> 4) << 3);
                uint32_t b0, b1, b2, b3;
                ldsm4t(b0, b1, b2, b3, bsB + (brow * GAST + bcol) * 2);
                #pragma unroll
                for (int mi = 0; mi < 2; mi++) {
                    mma16816(c[mi][nq * 2 + 0], a[mi], b0, b1);
                    mma16816(c[mi][nq * 2 + 1], a[mi], b2, b3);
                }
            }
        }
    }

    #pragma unroll
    for (int mi = 0; mi < 2; mi++) {
        #pragma unroll
        for (int ni = 0; ni < 4; ni++) {
            int row0 = m0 + wm * 32 + mi * 16 + (lane >> 2);
            int col = wn * 32 + ni * 8 + 2 * (lane & 3);
            float2 bv = *(const float2*)(g_bias0 + col);
            if (row0 < NN)
                *(__half2*)(g_ah + (size_t)row0 * 64 + col) = __floats2half2_rn(
                    fmaxf(c[mi][ni][0] + bv.x, 0.f), fmaxf(c[mi][ni][1] + bv.y, 0.f));
            int row1 = row0 + 8;
            if (row1 < NN)
                *(__half2*)(g_ah + (size_t)row1 * 64 + col) = __floats2half2_rn(
                    fmaxf(c[mi][ni][2] + bv.x, 0.f), fmaxf(c[mi][ni][3] + bv.y, 0.f));
        }
    }
}

// ---------------- persistent-A main GEMM: Y = Ah @ Wcat ---------------------
// ONE block barrier per tile: loadB(t+1) issued after the barrier, into the
// buffer freed by mma(t-1) (all warps provably past it).  [R13 structure]
#define AST 72
#define BST 136
#define CWST 72
#define PSMEM ((128 * AST + 2 * 64 * BST + 8 * 32 * CWST) * 2)   // 90112 B

__global__ void __launch_bounds__(256, 2)
gemmP_kernel(const __half* __restrict__ wc, int wstride,
             int tilesPerSplit, int ntilesTot, int ystride) {
    extern __shared__ __half sp[];
    __half* As = sp;                                   // [128][AST]
    __half* Bs0 = sp + 128 * AST;                      // [64][BST] x2
    __half* CsW = sp + 128 * AST + 2 * 64 * BST;       // 8 x [32][CWST]
    int m0 = blockIdx.x * 128;
    int t0 = blockIdx.y * tilesPerSplit;
    int t1 = min(ntilesTot, t0 + tilesPerSplit);
    int tid = threadIdx.x;
    int warp = tid >> 5, lane = tid & 31;
    int wm = warp & 3, wn = warp >> 2;
    __half* Cw = CsW + warp * 32 * CWST;

    // stage A once (plain stores; covered by first barrier)
    #pragma unroll
    for (int it = 0; it < 4; it++) {
        int idx = tid + it * 256;
        int row = idx >> 3;
        int c8 = idx & 7;
        uint4 v = make_uint4(0, 0, 0, 0);
        if (m0 + row < NN)
            v = __ldg((const uint4*)(g_ah + (size_t)(m0 + row) * 64 + c8 * 8));
        *(uint4*)(As + row * AST + c8 * 8) = v;
    }

    auto loadB = [&](int buf, int t) {
        uint32_t bb = (uint32_t)__cvta_generic_to_shared(Bs0 + buf * 64 * BST);
        int n0 = t * 128;
        #pragma unroll
        for (int it = 0; it < 4; it++) {
            int idx = tid + it * 256;      // 1024 x 16B
            int row = idx >> 4;
            int c8 = idx & 15;
            cpa16(bb + (row * BST + c8 * 8) * 2,
                  wc + (size_t)row * wstride + n0 + c8 * 8);
        }
        CP_COMMIT();
    };

    uint32_t asBase = (uint32_t)__cvta_generic_to_shared(As);
    loadB(0, t0);

    for (int t = t0; t < t1; t++) {
        int buf = (t - t0) & 1;
        CP_WAIT0();                                    // B(t) landed
        __syncthreads();                               // all warps past mma(t-1)
        if (t + 1 < t1) loadB(buf ^ 1, t + 1);         // into freed buffer

        uint32_t bsBase = (uint32_t)__cvta_generic_to_shared(Bs0 + buf * 64 * BST);
        float c[2][8][4];
        #pragma unroll
        for (int mi = 0; mi < 2; mi++)
            #pragma unroll
            for (int ni = 0; ni < 8; ni++)
                #pragma unroll
                for (int p = 0; p < 4; p++) c[mi][ni][p] = 0.f;

        #pragma unroll
        for (int ks = 0; ks < 4; ks++) {
            int k0 = ks * 16;
            uint32_t a[2][4];
            #pragma unroll
            for (int mi = 0; mi < 2; mi++) {
                int row = wm * 32 + mi * 16 + (lane & 15);
                int col = k0 + ((lane >> 4) << 3);
                ldsm4(a[mi][0], a[mi][1], a[mi][2], a[mi][3],
                      asBase + (row * AST + col) * 2);
            }
            #pragma unroll
            for (int nq = 0; nq < 4; nq++) {
                int row = k0 + (lane & 15);
                int col = wn * 64 + nq * 16 + ((lane >> 4) << 3);
                uint32_t b0, b1, b2, b3;
                ldsm4t(b0, b1, b2, b3, bsBase + (row * BST + col) * 2);
                #pragma unroll
                for (int mi = 0; mi < 2; mi++) {
                    mma16816(c[mi][nq * 2 + 0], a[mi], b0, b1);
                    mma16816(c[mi][nq * 2 + 1], a[mi], b2, b3);
                }
            }
        }

        // per-warp epilogue: fragments -> private Cs slice -> 128B row stores
        #pragma unroll
        for (int mi = 0; mi < 2; mi++) {
            #pragma unroll
            for (int ni = 0; ni < 8; ni++) {
                int r0 = mi * 16 + (lane >> 2);
                int col = ni * 8 + 2 * (lane & 3);
                *(__half2*)(Cw + r0 * CWST + col) =
                    __floats2half2_rn(c[mi][ni][0], c[mi][ni][1]);
                *(__half2*)(Cw + (r0 + 8) * CWST + col) =
                    __floats2half2_rn(c[mi][ni][2], c[mi][ni][3]);
            }
        }
        __syncwarp();
        int n0 = t * 128 + wn * 64;
        #pragma unroll
        for (int p = 0; p < 8; p++) {
            int row = p * 4 + (lane >> 3);
            int gr = m0 + wm * 32 + row;
            if (gr < NN) {
                uint4 v = *(const uint4*)(Cw + row * CWST + (lane & 7) * 8);
                *(uint4*)(g_y + (size_t)gr * ystride + n0 + (lane & 7) * 8) = v;
            }
        }
    }
}

// ---------------- gather for 64-wide layers (half2, dual accumulators) ------
template <bool RES, bool WF32>
__global__ void gather64_kernel(const float* __restrict__ bias,
                                const float* __restrict__ resid,
                                float* __restrict__ outF) {
    int warpId = (blockIdx.x * blockDim.x + threadIdx.x) >> 5;
    int lane = threadIdx.x & 31;
    if (warpId >= NN) return;
    int i = warpId;
    int e0 = g_rowp[i], e1 = g_rowp[i + 1];
    float2 accA = make_float2(0.f, 0.f);
    float2 accB = make_float2(0.f, 0.f);
    int e = e0;
    for (; e + 1 < e1; e += 2) {
        uint4 ed0 = __ldg(&g_ed[e]);
        uint4 ed1 = __ldg(&g_ed[e + 1]);
        {
            uint32_t jk = ed0.x;
            int j = jk & 0xFFFFF, kb = (jk >> 20) & 63;
            float w0 = __uint_as_float(ed0.y);
            float w1 = __uint_as_float(ed0.z);
            float w2 = __uint_as_float(ed0.w);
            float w3 = (float)(jk >> 31) - w0 - w1 - w2;
            const __half2* r = (const __half2*)(g_y + (size_t)j * YS1 + kb * 64 + 2 * lane);
            float2 f0 = __half22float2(__ldg(r));
            float2 f1 = __half22float2(__ldg(r + 32));
            float2 f2 = __half22float2(__ldg(r + 256));
            float2 f3 = __half22float2(__ldg(r + 288));
            accA.x += w0 * f0.x + w1 * f1.x + w2 * f2.x + w3 * f3.x;
            accA.y += w0 * f0.y + w1 * f1.y + w2 * f2.y + w3 * f3.y;
        }
        {
            uint32_t jk = ed1.x;
            int j = jk & 0xFFFFF, kb = (jk >> 20) & 63;
            float w0 = __uint_as_float(ed1.y);
            float w1 = __uint_as_float(ed1.z);
            float w2 = __uint_as_float(ed1.w);
            float w3 = (float)(jk >> 31) - w0 - w1 - w2;
            const __half2* r = (const __half2*)(g_y + (size_t)j * YS1 + kb * 64 + 2 * lane);
            float2 f0 = __half22float2(__ldg(r));
            float2 f1 = __half22float2(__ldg(r + 32));
            float2 f2 = __half22float2(__ldg(r + 256));
            float2 f3 = __half22float2(__ldg(r + 288));
            accB.x += w0 * f0.x + w1 * f1.x + w2 * f2.x + w3 * f3.x;
            accB.y += w0 * f0.y + w1 * f1.y + w2 * f2.y + w3 * f3.y;
        }
    }
    if (e < e1) {
        uint4 ed0 = __ldg(&g_ed[e]);
        uint32_t jk = ed0.x;
        int j = jk & 0xFFFFF, kb = (jk >> 20) & 63;
        float w0 = __uint_as_float(ed0.y);
        float w1 = __uint_as_float(ed0.z);
        float w2 = __uint_as_float(ed0.w);
        float w3 = (float)(jk >> 31) - w0 - w1 - w2;
        const __half2* r = (const __half2*)(g_y + (size_t)j * YS1 + kb * 64 + 2 * lane);
        float2 f0 = __half22float2(__ldg(r));
        float2 f1 = __half22float2(__ldg(r + 32));
        float2 f2 = __half22float2(__ldg(r + 256));
        float2 f3 = __half22float2(__ldg(r + 288));
        accA.x += w0 * f0.x + w1 * f1.x + w2 * f2.x + w3 * f3.x;
        accA.y += w0 * f0.y + w1 * f1.y + w2 * f2.y + w3 * f3.y;
    }
    float2 acc = make_float2(accA.x + accB.x, accA.y + accB.y);
    float2 s = __half22float2(*(const __half2*)(g_y + (size_t)i * YS1 + 4096 + 2 * lane));
    float2 bv = *(const float2*)(bias + 2 * lane);
    float2 o = make_float2(acc.x + s.x + bv.x, acc.y + s.y + bv.y);
    if (RES) {
        float2 rv = *(const float2*)(resid + (size_t)i * 64 + 2 * lane);
        o.x += rv.x; o.y += rv.y;
    }
    if (WF32)
        *(float2*)(outF + (size_t)i * 64 + 2 * lane) = o;
    *(__half2*)(g_ah + (size_t)i * 64 + 2 * lane) =
        __floats2half2_rn(fmaxf(o.x, 0.f), fmaxf(o.y, 0.f));
}

// ---------------- final gather (Cout = 2) + /128 ----------------------------
__global__ void gatherF_kernel(const float* __restrict__ cb3,
                               const float* __restrict__ fb3,
                               float* __restrict__ out) {
    int warpId = (blockIdx.x * blockDim.x + threadIdx.x) >> 5;
    int lane = threadIdx.x & 31;
    if (warpId >= NN) return;
    int i = warpId;
    int e0 = g_rowp[i], e1 = g_rowp[i + 1];
    float accx = 0.f, accy = 0.f;
    for (int e = e0 + lane; e < e1; e += 32) {
        uint4 ed = __ldg(&g_ed[e]);
        uint32_t jk = ed.x;
        int j = jk & 0xFFFFF, kb = (jk >> 20) & 63;
        float w0 = __uint_as_float(ed.y);
        float w1 = __uint_as_float(ed.z);
        float w2 = __uint_as_float(ed.w);
        float w3 = (float)(jk >> 31) - w0 - w1 - w2;
        const __half2* r = (const __half2*)(g_y + (size_t)j * YS3 + kb * 2);
        float2 f0 = __half22float2(__ldg(r));
        float2 f1 = __half22float2(__ldg(r + 1));
        float2 f2 = __half22float2(__ldg(r + 8));
        float2 f3 = __half22float2(__ldg(r + 9));
        accx += w0 * f0.x + w1 * f1.x + w2 * f2.x + w3 * f3.x;
        accy += w0 * f0.y + w1 * f1.y + w2 * f2.y + w3 * f3.y;
    }
    #pragma unroll
    for (int off = 16; off > 0; off >>= 1) {
        accx += __shfl_down_sync(0xFFFFFFFFu, accx, off);
        accy += __shfl_down_sync(0xFFFFFFFFu, accy, off);
    }
    if (lane == 0) {
        float2 ds = __half22float2(*(const __half2*)(g_y + (size_t)i * YS3 + 128));
        out[2 * i]     = (accx + ds.x + cb3[0] + fb3[0]) * (1.f / 128.f);
        out[2 * i + 1] = (accy + ds.y + cb3[1] + fb3[1]) * (1.f / 128.f);
    }
}

// ---------------- launch ----------------------------------------------------
extern "C" void kernel_launch(void* const* d_in, const int* in_sizes, int n_in,
                              void* d_out, int out_size) {
    const float* pos  = (const float*)d_in[0];
    const float* feat = (const float*)d_in[1];
    const int*   ei   = (const int*)d_in[2];
    const int*   ej   = (const int*)d_in[3];
    const float* cw0 = (const float*)d_in[4];
    const float* cb0 = (const float*)d_in[5];
    const float* fw0 = (const float*)d_in[6];
    const float* fb0 = (const float*)d_in[7];
    const float* cw1 = (const float*)d_in[8];
    const float* cb1 = (const float*)d_in[9];
    const float* fw1 = (const float*)d_in[10];
    const float* fb1 = (const float*)d_in[11];
    const float* cw2 = (const float*)d_in[12];
    const float* cb2 = (const float*)d_in[13];
    const float* fw2 = (const float*)d_in[14];
    const float* fb2 = (const float*)d_in[15];
    const float* cw3 = (const float*)d_in[16];
    const float* cb3 = (const float*)d_in[17];
    const float* fw3 = (const float*)d_in[18];
    const float* fb3 = (const float*)d_in[19];
    float* out = (float*)d_out;
    int E = in_sizes[2];

    cudaFuncSetAttribute(gemmA_kernel,
                         cudaFuncAttributeMaxDynamicSharedMemorySize, SMEMA);
    cudaFuncSetAttribute(gemmP_kernel,
                         cudaFuncAttributeMaxDynamicSharedMemorySize, PSMEM);

    float* aF;  cudaGetSymbolAddress((void**)&aF, g_ansF);
    __half* w1; cudaGetSymbolAddress((void**)&w1, g_wc1);
    __half* w2; cudaGetSymbolAddress((void**)&w2, g_wc2);
    __half* w3; cudaGetSymbolAddress((void**)&w3, g_wc3);
    float* b1;  cudaGetSymbolAddress((void**)&b1, g_bias1);
    float* b2;  cudaGetSymbolAddress((void**)&b2, g_bias2);

    // zero cnt, then fused weight pack + hist (independent jobs co-scheduled)
    zero_cnt_kernel<<<(NN + 256) / 256, 256>>>();
    packHist_kernel<<<PACK_BLK + HIST_BLK, 256>>>(
        cw0, fw0, cb0, fb0, cw1, fw1, cb1, fb1,
        cw2, fw2, cb2, fb2, cw3, fw3, ei, E);

    // scans + scatter
    scan1_kernel<<<SCAN_B, 1024>>>();
    scan2_kernel<<<1, 64>>>();
    scan3_kernel<<<SCAN_B, 1024>>>();
    scatter_kernel<<<(E + 255) / 256, 256>>>(pos, ei, ej, E);

    // layer 0 (moment formulation)
    mom0_kernel<<<NN / 8, 256>>>(feat);
    gemmA_kernel<<<391, 256, SMEMA>>>();

    // layer 1
    gemmP_kernel<<<dim3(391, 3), 256, PSMEM>>>(w1, NPAD, 11, 33, YS1);
    gather64_kernel<false, true><<<(NN * 32 + 255) / 256, 256>>>(b1, nullptr, aF);

    // layer 2 (residual = ansF)
    gemmP_kernel<<<dim3(391, 3), 256, PSMEM>>>(w2, NPAD, 11, 33, YS1);
    gather64_kernel<true, false><<<(NN * 32 + 255) / 256, 256>>>(b2, aF, nullptr);

    // layer 3
    gemmP_kernel<<<dim3(391, 2), 256, PSMEM>>>(w3, 256, 1, 2, YS3);
    gatherF_kernel<<<(NN * 32 + 255) / 256, 256>>>(cb3, fb3, out);
}

// round 17
// speedup vs baseline: 1.0103x; 1.0103x over previous
#include <cuda_runtime.h>
#include <cuda_fp16.h>
#include <stdint.h>

#define NN 50000
#define EE 1600000
#define YS1 4224          // padded y stride (halves) for 64->64 layers (33*128)
#define YS3 256           // y stride for layer3
#define NPAD 4224         // packed-weight column pad (layers 1/2)
#define SCAN_B 49         // ceil(50000/1024)

// ---------------- device scratch (no runtime allocation allowed) ------------
__device__ __align__(16) __half g_y[(size_t)NN * YS1];   // 422 MB
__device__ __align__(16) __half g_wc1[64 * NPAD];
__device__ __align__(16) __half g_wc2[64 * NPAD];
__device__ __align__(16) __half g_wc3[64 * 256];
__device__ __align__(16) __half g_ah[NN * 64];           // relu(ans) fp16 (GEMM A)
__device__ __align__(16) __half g_resH[NN * 64];         // layer1 out fp16 (residual)
__device__ __align__(16) __half g_m0[(size_t)NN * 320];  // layer0 moments + x, fp16
__device__ __align__(16) __half g_wb0[320 * 64];         // layer0 packed weights
__device__ float  g_bias0[64];
__device__ float  g_bias1[64];
__device__ float  g_bias2[64];
__device__ int    g_cnt[NN + 1];
__device__ int    g_rowp[NN + 1];
__device__ int    g_rank[EE];
__device__ int    g_bsum[SCAN_B];
__device__ int    g_boff[SCAN_B + 1];
// edge record: .x = j | kb<<20 | m<<31 ; .y/.z/.w = w0,w1,w2 (fp32 bits)
__device__ __align__(16) uint4 g_ed[EE];

// ---------------- mma / async helpers ----------------------------------------
__device__ __forceinline__ void ldsm4(uint32_t& r0, uint32_t& r1, uint32_t& r2,
                                      uint32_t& r3, uint32_t addr) {
    asm volatile("ldmatrix.sync.aligned.m8n8.x4.shared.b16 {%0,%1,%2,%3}, [%4];"
                 : "=r"(r0), "=r"(r1), "=r"(r2), "=r"(r3) : "r"(addr));
}
__device__ __forceinline__ void ldsm4t(uint32_t& r0, uint32_t& r1, uint32_t& r2,
                                       uint32_t& r3, uint32_t addr) {
    asm volatile("ldmatrix.sync.aligned.m8n8.x4.trans.shared.b16 {%0,%1,%2,%3}, [%4];"
                 : "=r"(r0), "=r"(r1), "=r"(r2), "=r"(r3) : "r"(addr));
}
__device__ __forceinline__ void mma16816(float* c, const uint32_t* a,
                                         uint32_t b0, uint32_t b1) {
    asm volatile(
        "mma.sync.aligned.m16n8k16.row.col.f32.f16.f16.f32 "
        "{%0,%1,%2,%3}, {%4,%5,%6,%7}, {%8,%9}, {%0,%1,%2,%3};"
        : "+f"(c[0]), "+f"(c[1]), "+f"(c[2]), "+f"(c[3])
        : "r"(a[0]), "r"(a[1]), "r"(a[2]), "r"(a[3]), "r"(b0), "r"(b1));
}
__device__ __forceinline__ void cpa16(uint32_t dst, const void* src) {
    asm volatile("cp.async.cg.shared.global [%0], [%1], 16;" :: "r"(dst), "l"(src));
}
__device__ __forceinline__ void cpa16z(uint32_t dst, const void* src, int nbytes) {
    asm volatile("cp.async.cg.shared.global [%0], [%1], 16, %2;"
                 :: "r"(dst), "l"(src), "r"(nbytes));
}
#define CP_COMMIT() asm volatile("cp.async.commit_group;")
#define CP_WAIT0()  asm volatile("cp.async.wait_group 0;")

// ---------------- combined weight pack + cnt zero ----------------------------
#define R0 (320 * 64)
#define R1 (64 * NPAD)
#define R3 (64 * 256)
#define PACK_TOT (R0 + 2 * R1 + R3 + NN + 1)

__device__ __forceinline__ float wcat_val(const float* CW, const float* FW,
                                          int k, int col, int ncols,
                                          int coutShift, int coutMask) {
    if (col >= ncols) return 0.f;
    int cout = 1 << coutShift;
    int kcoutTot = 64 << coutShift;
    if (col < kcoutTot) {
        int kk = col >> coutShift;
        int co = col & coutMask;
        return __ldg(CW + (size_t)(kk * 64 + k) * cout + co);
    }
    return __ldg(FW + (size_t)k * cout + (col - kcoutTot));
}

__global__ void packAll_kernel(
    const float* __restrict__ cw0, const float* __restrict__ fw0,
    const float* __restrict__ cb0, const float* __restrict__ fb0,
    const float* __restrict__ cw1, const float* __restrict__ fw1,
    const float* __restrict__ cb1, const float* __restrict__ fb1,
    const float* __restrict__ cw2, const float* __restrict__ fw2,
    const float* __restrict__ cb2, const float* __restrict__ fb2,
    const float* __restrict__ cw3, const float* __restrict__ fw3) {
    int idx = blockIdx.x * blockDim.x + threadIdx.x;
    if (idx >= PACK_TOT) return;
    if (idx < R0) {
        int row = idx >> 6, co = idx & 63;
        float v = 0.f;
        if (row < 256) {
            int kb = row >> 2, c = row & 3;
            if (co >= 32) v = __ldg(cw0 + (size_t)(kb * 4 + c) * 32 + (co - 32));
        } else if (row < 260) {
            int c = row - 256;
            if (co < 32) v = __ldg(fw0 + (size_t)c * 32 + co);
        }
        g_wb0[idx] = __float2half(v);
        if (idx < 64)
            g_bias0[idx] = (idx < 32) ? __ldg(fb0 + idx) : __ldg(cb0 + idx - 32);
        return;
    }
    idx -= R0;
    if (idx < R1) {
        int k = idx / NPAD, col = idx - k * NPAD;
        g_wc1[idx] = __float2half(wcat_val(cw1, fw1, k, col, 4160, 6, 63));
        if (idx < 64) g_bias1[idx] = __ldg(cb1 + idx) + __ldg(fb1 + idx);
        return;
    }
    idx -= R1;
    if (idx < R1) {
        int k = idx / NPAD, col = idx - k * NPAD;
        g_wc2[idx] = __float2half(wcat_val(cw2, fw2, k, col, 4160, 6, 63));
        if (idx < 64) g_bias2[idx] = __ldg(cb2 + idx) + __ldg(fb2 + idx);
        return;
    }
    idx -= R1;
    if (idx < R3) {
        int k = idx >> 8, col = idx & 255;
        g_wc3[idx] = __float2half(wcat_val(cw3, fw3, k, col, 130, 1, 1));
        return;
    }
    idx -= R3;
    g_cnt[idx] = 0;
}

// ---------------- edge preprocessing ----------------------------------------
__global__ void hist_kernel(const int* __restrict__ ei, int E) {
    int e = blockIdx.x * blockDim.x + threadIdx.x;
    if (e < E) g_rank[e] = atomicAdd(&g_cnt[__ldg(ei + e)], 1);
}

// full local exclusive scan -> g_rowp (pre-offset); block total -> g_bsum
__global__ void scan1_kernel() {
    __shared__ int sh[1024];
    int b = blockIdx.x, tid = threadIdx.x;
    int idx = b * 1024 + tid;
    int v = (idx < NN) ? g_cnt[idx] : 0;
    int orig = v;
    sh[tid] = v;
    __syncthreads();
    for (int off = 1; off < 1024; off <<= 1) {
        int t = (tid >= off) ? sh[tid - off] : 0;
        __syncthreads();
        sh[tid] += t;
        __syncthreads();
    }
    if (idx < NN) g_rowp[idx] = sh[tid] - orig;
    if (tid == 1023) g_bsum[b] = sh[1023];
}

__global__ void scan2_kernel() {
    __shared__ int sh[64];
    int tid = threadIdx.x;
    int v = (tid < SCAN_B) ? g_bsum[tid] : 0;
    sh[tid] = v;
    __syncthreads();
    for (int off = 1; off < 64; off <<= 1) {
        int t = (tid >= off) ? sh[tid - off] : 0;
        __syncthreads();
        sh[tid] += t;
        __syncthreads();
    }
    if (tid < SCAN_B) g_boff[tid] = sh[tid] - v;
    if (tid == SCAN_B - 1) g_boff[SCAN_B] = sh[tid];
}

// add block offset (trivial elementwise pass)
__global__ void scan3_kernel() {
    int b = blockIdx.x, tid = threadIdx.x;
    int idx = b * 1024 + tid;
    if (idx < NN) g_rowp[idx] += g_boff[b];
    if (b == 0 && tid == 0) g_rowp[NN] = g_boff[SCAN_B];
}

__global__ void scatter_kernel(const float* __restrict__ pos,
                               const int* __restrict__ ei,
                               const int* __restrict__ ej, int E) {
    int e = blockIdx.x * blockDim.x + threadIdx.x;
    if (e >= E) return;
    int i = __ldg(ei + e), j = __ldg(ej + e);
    const float2* p2 = (const float2*)pos;
    float2 pi = __ldg(p2 + i);
    float2 pj = __ldg(p2 + j);
    float dx = pi.x - pj.x;
    float dy = pi.y - pj.y;
    dx = fminf(1.f, fmaxf(-1.f, dx));
    dy = fminf(1.f, fmaxf(-1.f, dy));
    uint32_t m = (i != j) ? 1u : 0u;
    float mf = (float)m;
    float r = sqrtf(dx * dx + dy * dy + 1e-12f);
    float u = fminf(1.f, fmaxf(-1.f, 2.f * r - 1.f));
    float v = atan2f(dy, dx) * 0.318309886183790672f;   // 1/pi
    float su = (u + 1.f) * 3.5f;
    int   iu = min(6, (int)floorf(su));
    float tu = su - (float)iu;
    float sv = (v + 1.f) * 3.5f;
    int   iv = min(6, (int)floorf(sv));
    float tv = sv - (float)iv;
    float w0 = (1.f - tu) * (1.f - tv) * mf;
    float w1 = (1.f - tu) * tv * mf;
    float w2 = tu * (1.f - tv) * mf;
    uint32_t kb = (uint32_t)(iu * 8 + iv);
    int p = g_rowp[i] + g_rank[e];
    uint4 ed;
    ed.x = (uint32_t)j | (kb << 20) | (m << 31);
    ed.y = __float_as_uint(w0);
    ed.z = __float_as_uint(w1);
    ed.w = __float_as_uint(w2);
    g_ed[p] = ed;
}

// ---------------- layer 0: moment accumulation (dual-edge, Cin=4) -----------
__global__ void mom0_kernel(const float* __restrict__ X) {
    __shared__ float M0s[8 * 512];
    int warp = threadIdx.x >> 5, lane = threadIdx.x & 31;
    int node = blockIdx.x * 8 + warp;
    float* M = M0s + warp * 512;
    #pragma unroll
    for (int r = 0; r < 16; r++) M[r * 32 + lane] = 0.f;
    __syncwarp();
    if (node < NN) {
        int e0 = g_rowp[node], e1 = g_rowp[node + 1];
        int p = lane >> 4;                 // edge parity
        int t = (lane >> 2) & 3;           // tap
        int c = lane & 3;                  // channel
        int kadd = (t & 1) + ((t >> 1) << 3);
        float* Mp = M + p * 256;
        for (int e = e0; e < e1; e += 2) {
            int ee = e + p;
            if (ee < e1) {
                uint4 ed = __ldg(&g_ed[ee]);
                uint32_t jk = ed.x;
                int j = jk & 0xFFFFF;
                int kb = (jk >> 20) & 63;
                float w0 = __uint_as_float(ed.y);
                float w1 = __uint_as_float(ed.z);
                float w2 = __uint_as_float(ed.w);
                float w3 = (float)(jk >> 31) - w0 - w1 - w2;
                float4 xv = __ldg((const float4*)X + j);
                float wt = (t == 0) ? w0 : (t == 1) ? w1 : (t == 2) ? w2 : w3;
                float xc = (c == 0) ? xv.x : (c == 1) ? xv.y : (c == 2) ? xv.z : xv.w;
                Mp[(kb + kadd) * 4 + c] += wt * xc;
            }
        }
        __syncwarp();
        __half* dst = g_m0 + (size_t)node * 320;
        #pragma unroll
        for (int r = 0; r < 4; r++) {
            int idx = r * 64 + 2 * lane;
            float v0 = M[idx] + M[256 + idx];
            float v1 = M[idx + 1] + M[256 + idx + 1];
            *(__half2*)(dst + idx) = __floats2half2_rn(v0, v1);
        }
        float4 xi = __ldg((const float4*)X + node);
        __half2 hv;
        if (lane == 0)      hv = __floats2half2_rn(xi.x, xi.y);
        else if (lane == 1) hv = __floats2half2_rn(xi.z, xi.w);
        else                hv = __floats2half2_rn(0.f, 0.f);
        *(__half2*)(dst + 256 + 2 * lane) = hv;
    }
}

// ---------------- layer 0 GEMM: ans0 = [M0|x] @ Wb0, bias, relu -> g_ah -----
#define GAST 72
#define SMEMA ((2 * 128 * GAST + 320 * GAST) * 2)   // 82944 B

__global__ void __launch_bounds__(256)
gemmA_kernel() {
    extern __shared__ __half smA[];
    __half* Ab0 = smA;
    __half* Ab1 = smA + 128 * GAST;
    __half* Bs = smA + 2 * 128 * GAST;   // [320][GAST]
    int m0 = blockIdx.x * 128;
    int tid = threadIdx.x;

    #pragma unroll
    for (int it = 0; it < 10; it++) {
        int idx = tid + it * 256;
        int row = idx >> 3;
        int c8 = idx & 7;
        uint4 v = __ldg((const uint4*)(g_wb0 + row * 64 + c8 * 8));
        *(uint4*)(Bs + row * GAST + c8 * 8) = v;
    }

    auto loadA = [&](__half* dst, int kc) {
        uint32_t ab = (uint32_t)__cvta_generic_to_shared(dst);
        #pragma unroll
        for (int it = 0; it < 4; it++) {
            int idx = tid + it * 256;
            int row = idx >> 3;
            int c8 = idx & 7;
            int nb = (m0 + row < NN) ? 16 : 0;
            cpa16z(ab + (row * GAST + c8 * 8) * 2,
                   g_m0 + (size_t)(m0 + row) * 320 + kc * 64 + c8 * 8, nb);
        }
        CP_COMMIT();
    };

    int warp = tid >> 5, lane = tid & 31;
    int wm = warp & 3, wn = warp >> 2;
    uint32_t bsB = (uint32_t)__cvta_generic_to_shared(Bs);

    float c[2][4][4];
    #pragma unroll
    for (int mi = 0; mi < 2; mi++)
        #pragma unroll
        for (int ni = 0; ni < 4; ni++)
            #pragma unroll
            for (int p = 0; p < 4; p++) c[mi][ni][p] = 0.f;

    loadA(Ab0, 0);
    for (int kc = 0; kc < 5; kc++) {
        CP_WAIT0();
        __syncthreads();
        if (kc < 4) loadA((kc & 1) ? Ab0 : Ab1, kc + 1);
        uint32_t asB = (uint32_t)__cvta_generic_to_shared((kc & 1) ? Ab1 : Ab0);
        #pragma unroll
        for (int ks = 0; ks < 4; ks++) {
            int k0 = ks * 16;
            uint32_t a[2][4];
            #pragma unroll
            for (int mi = 0; mi < 2; mi++) {
                int row = wm * 32 + mi * 16 + (lane & 15);
                int col = k0 + ((lane >> 4) << 3);
                ldsm4(a[mi][0], a[mi][1], a[mi][2], a[mi][3],
                      asB + (row * GAST + col) * 2);
            }
            int brow = kc * 64 + k0 + (lane & 15);
            #pragma unroll
            for (int nq = 0; nq < 2; nq++) {
                int bcol = wn * 32 + nq * 16 + ((lane >> 4) << 3);
                uint32_t b0, b1, b2, b3;
                ldsm4t(b0, b1, b2, b3, bsB + (brow * GAST + bcol) * 2);
                #pragma unroll
                for (int mi = 0; mi < 2; mi++) {
                    mma16816(c[mi][nq * 2 + 0], a[mi], b0, b1);
                    mma16816(c[mi][nq * 2 + 1], a[mi], b2, b3);
                }
            }
        }
    }

    #pragma unroll
    for (int mi = 0; mi < 2; mi++) {
        #pragma unroll
        for (int ni = 0; ni < 4; ni++) {
            int row0 = m0 + wm * 32 + mi * 16 + (lane >> 2);
            int col = wn * 32 + ni * 8 + 2 * (lane & 3);
            float2 bv = *(const float2*)(g_bias0 + col);
            if (row0 < NN)
                *(__half2*)(g_ah + (size_t)row0 * 64 + col) = __floats2half2_rn(
                    fmaxf(c[mi][ni][0] + bv.x, 0.f), fmaxf(c[mi][ni][1] + bv.y, 0.f));
            int row1 = row0 + 8;
            if (row1 < NN)
                *(__half2*)(g_ah + (size_t)row1 * 64 + col) = __floats2half2_rn(
                    fmaxf(c[mi][ni][2] + bv.x, 0.f), fmaxf(c[mi][ni][3] + bv.y, 0.f));
        }
    }
}

// ---------------- persistent-A main GEMM: Y = Ah @ Wcat ---------------------
// ONE block barrier per tile: loadB(t+1) issued after the barrier, into the
// buffer freed by mma(t-1) (all warps provably past it).  [R13 structure]
#define AST 72
#define BST 136
#define CWST 72
#define PSMEM ((128 * AST + 2 * 64 * BST + 8 * 32 * CWST) * 2)   // 90112 B

__global__ void __launch_bounds__(256, 2)
gemmP_kernel(const __half* __restrict__ wc, int wstride,
             int tilesPerSplit, int ntilesTot, int ystride) {
    extern __shared__ __half sp[];
    __half* As = sp;                                   // [128][AST]
    __half* Bs0 = sp + 128 * AST;                      // [64][BST] x2
    __half* CsW = sp + 128 * AST + 2 * 64 * BST;       // 8 x [32][CWST]
    int m0 = blockIdx.x * 128;
    int t0 = blockIdx.y * tilesPerSplit;
    int t1 = min(ntilesTot, t0 + tilesPerSplit);
    int tid = threadIdx.x;
    int warp = tid >> 5, lane = tid & 31;
    int wm = warp & 3, wn = warp >> 2;
    __half* Cw = CsW + warp * 32 * CWST;

    // stage A once (plain stores; covered by first barrier)
    #pragma unroll
    for (int it = 0; it < 4; it++) {
        int idx = tid + it * 256;
        int row = idx >> 3;
        int c8 = idx & 7;
        uint4 v = make_uint4(0, 0, 0, 0);
        if (m0 + row < NN)
            v = __ldg((const uint4*)(g_ah + (size_t)(m0 + row) * 64 + c8 * 8));
        *(uint4*)(As + row * AST + c8 * 8) = v;
    }

    auto loadB = [&](int buf, int t) {
        uint32_t bb = (uint32_t)__cvta_generic_to_shared(Bs0 + buf * 64 * BST);
        int n0 = t * 128;
        #pragma unroll
        for (int it = 0; it < 4; it++) {
            int idx = tid + it * 256;      // 1024 x 16B
            int row = idx >> 4;
            int c8 = idx & 15;
            cpa16(bb + (row * BST + c8 * 8) * 2,
                  wc + (size_t)row * wstride + n0 + c8 * 8);
        }
        CP_COMMIT();
    };

    uint32_t asBase = (uint32_t)__cvta_generic_to_shared(As);
    loadB(0, t0);

    for (int t = t0; t < t1; t++) {
        int buf = (t - t0) & 1;
        CP_WAIT0();                                    // B(t) landed
        __syncthreads();                               // all warps past mma(t-1)
        if (t + 1 < t1) loadB(buf ^ 1, t + 1);         // into freed buffer

        uint32_t bsBase = (uint32_t)__cvta_generic_to_shared(Bs0 + buf * 64 * BST);
        float c[2][8][4];
        #pragma unroll
        for (int mi = 0; mi < 2; mi++)
            #pragma unroll
            for (int ni = 0; ni < 8; ni++)
                #pragma unroll
                for (int p = 0; p < 4; p++) c[mi][ni][p] = 0.f;

        #pragma unroll
        for (int ks = 0; ks < 4; ks++) {
            int k0 = ks * 16;
            uint32_t a[2][4];
            #pragma unroll
            for (int mi = 0; mi < 2; mi++) {
                int row = wm * 32 + mi * 16 + (lane & 15);
                int col = k0 + ((lane >> 4) << 3);
                ldsm4(a[mi][0], a[mi][1], a[mi][2], a[mi][3],
                      asBase + (row * AST + col) * 2);
            }
            #pragma unroll
            for (int nq = 0; nq < 4; nq++) {
                int row = k0 + (lane & 15);
                int col = wn * 64 + nq * 16 + ((lane >> 4) << 3);
                uint32_t b0, b1, b2, b3;
                ldsm4t(b0, b1, b2, b3, bsBase + (row * BST + col) * 2);
                #pragma unroll
                for (int mi = 0; mi < 2; mi++) {
                    mma16816(c[mi][nq * 2 + 0], a[mi], b0, b1);
                    mma16816(c[mi][nq * 2 + 1], a[mi], b2, b3);
                }
            }
        }

        // per-warp epilogue: fragments -> private Cs slice -> 128B row stores
        #pragma unroll
        for (int mi = 0; mi < 2; mi++) {
            #pragma unroll
            for (int ni = 0; ni < 8; ni++) {
                int r0 = mi * 16 + (lane >> 2);
                int col = ni * 8 + 2 * (lane & 3);
                *(__half2*)(Cw + r0 * CWST + col) =
                    __floats2half2_rn(c[mi][ni][0], c[mi][ni][1]);
                *(__half2*)(Cw + (r0 + 8) * CWST + col) =
                    __floats2half2_rn(c[mi][ni][2], c[mi][ni][3]);
            }
        }
        __syncwarp();
        int n0 = t * 128 + wn * 64;
        #pragma unroll
        for (int p = 0; p < 8; p++) {
            int row = p * 4 + (lane >> 3);
            int gr = m0 + wm * 32 + row;
            if (gr < NN) {
                uint4 v = *(const uint4*)(Cw + row * CWST + (lane & 7) * 8);
                *(uint4*)(g_y + (size_t)gr * ystride + n0 + (lane & 7) * 8) = v;
            }
        }
    }
}

// ---------------- gather for 64-wide layers (half2, dual accumulators) ------
// RES: add fp16 residual; WRES: write pre-relu ans as fp16 residual
template <bool RES, bool WRES>
__global__ void gather64_kernel(const float* __restrict__ bias) {
    int warpId = (blockIdx.x * blockDim.x + threadIdx.x) >> 5;
    int lane = threadIdx.x & 31;
    if (warpId >= NN) return;
    int i = warpId;
    int e0 = g_rowp[i], e1 = g_rowp[i + 1];
    float2 accA = make_float2(0.f, 0.f);
    float2 accB = make_float2(0.f, 0.f);
    int e = e0;
    for (; e + 1 < e1; e += 2) {
        uint4 ed0 = __ldg(&g_ed[e]);
        uint4 ed1 = __ldg(&g_ed[e + 1]);
        {
            uint32_t jk = ed0.x;
            int j = jk & 0xFFFFF, kb = (jk >> 20) & 63;
            float w0 = __uint_as_float(ed0.y);
            float w1 = __uint_as_float(ed0.z);
            float w2 = __uint_as_float(ed0.w);
            float w3 = (float)(jk >> 31) - w0 - w1 - w2;
            const __half2* r = (const __half2*)(g_y + (size_t)j * YS1 + kb * 64 + 2 * lane);
            float2 f0 = __half22float2(__ldg(r));
            float2 f1 = __half22float2(__ldg(r + 32));
            float2 f2 = __half22float2(__ldg(r + 256));
            float2 f3 = __half22float2(__ldg(r + 288));
            accA.x += w0 * f0.x + w1 * f1.x + w2 * f2.x + w3 * f3.x;
            accA.y += w0 * f0.y + w1 * f1.y + w2 * f2.y + w3 * f3.y;
        }
        {
            uint32_t jk = ed1.x;
            int j = jk & 0xFFFFF, kb = (jk >> 20) & 63;
            float w0 = __uint_as_float(ed1.y);
            float w1 = __uint_as_float(ed1.z);
            float w2 = __uint_as_float(ed1.w);
            float w3 = (float)(jk >> 31) - w0 - w1 - w2;
            const __half2* r = (const __half2*)(g_y + (size_t)j * YS1 + kb * 64 + 2 * lane);
            float2 f0 = __half22float2(__ldg(r));
            float2 f1 = __half22float2(__ldg(r + 32));
            float2 f2 = __half22float2(__ldg(r + 256));
            float2 f3 = __half22float2(__ldg(r + 288));
            accB.x += w0 * f0.x + w1 * f1.x + w2 * f2.x + w3 * f3.x;
            accB.y += w0 * f0.y + w1 * f1.y + w2 * f2.y + w3 * f3.y;
        }
    }
    if (e < e1) {
        uint4 ed0 = __ldg(&g_ed[e]);
        uint32_t jk = ed0.x;
        int j = jk & 0xFFFFF, kb = (jk >> 20) & 63;
        float w0 = __uint_as_float(ed0.y);
        float w1 = __uint_as_float(ed0.z);
        float w2 = __uint_as_float(ed0.w);
        float w3 = (float)(jk >> 31) - w0 - w1 - w2;
        const __half2* r = (const __half2*)(g_y + (size_t)j * YS1 + kb * 64 + 2 * lane);
        float2 f0 = __half22float2(__ldg(r));
        float2 f1 = __half22float2(__ldg(r + 32));
        float2 f2 = __half22float2(__ldg(r + 256));
        float2 f3 = __half22float2(__ldg(r + 288));
        accA.x += w0 * f0.x + w1 * f1.x + w2 * f2.x + w3 * f3.x;
        accA.y += w0 * f0.y + w1 * f1.y + w2 * f2.y + w3 * f3.y;
    }
    float2 acc = make_float2(accA.x + accB.x, accA.y + accB.y);
    float2 s = __half22float2(*(const __half2*)(g_y + (size_t)i * YS1 + 4096 + 2 * lane));
    float2 bv = *(const float2*)(bias + 2 * lane);
    float2 o = make_float2(acc.x + s.x + bv.x, acc.y + s.y + bv.y);
    if (RES) {
        float2 rv = __half22float2(*(const __half2*)(g_resH + (size_t)i * 64 + 2 * lane));
        o.x += rv.x; o.y += rv.y;
    }
    if (WRES)
        *(__half2*)(g_resH + (size_t)i * 64 + 2 * lane) = __floats2half2_rn(o.x, o.y);
    *(__half2*)(g_ah + (size_t)i * 64 + 2 * lane) =
        __floats2half2_rn(fmaxf(o.x, 0.f), fmaxf(o.y, 0.f));
}

// ---------------- final gather (Cout = 2) + /128 ----------------------------
__global__ void gatherF_kernel(const float* __restrict__ cb3,
                               const float* __restrict__ fb3,
                               float* __restrict__ out) {
    int warpId = (blockIdx.x * blockDim.x + threadIdx.x) >> 5;
    int lane = threadIdx.x & 31;
    if (warpId >= NN) return;
    int i = warpId;
    int e0 = g_rowp[i], e1 = g_rowp[i + 1];
    float accx = 0.f, accy = 0.f;
    for (int e = e0 + lane; e < e1; e += 32) {
        uint4 ed = __ldg(&g_ed[e]);
        uint32_t jk = ed.x;
        int j = jk & 0xFFFFF, kb = (jk >> 20) & 63;
        float w0 = __uint_as_float(ed.y);
        float w1 = __uint_as_float(ed.z);
        float w2 = __uint_as_float(ed.w);
        float w3 = (float)(jk >> 31) - w0 - w1 - w2;
        const __half2* r = (const __half2*)(g_y + (size_t)j * YS3 + kb * 2);
        float2 f0 = __half22float2(__ldg(r));
        float2 f1 = __half22float2(__ldg(r + 1));
        float2 f2 = __half22float2(__ldg(r + 8));
        float2 f3 = __half22float2(__ldg(r + 9));
        accx += w0 * f0.x + w1 * f1.x + w2 * f2.x + w3 * f3.x;
        accy += w0 * f0.y + w1 * f1.y + w2 * f2.y + w3 * f3.y;
    }
    #pragma unroll
    for (int off = 16; off > 0; off >>= 1) {
        accx += __shfl_down_sync(0xFFFFFFFFu, accx, off);
        accy += __shfl_down_sync(0xFFFFFFFFu, accy, off);
    }
    if (lane == 0) {
        float2 ds = __half22float2(*(const __half2*)(g_y + (size_t)i * YS3 + 128));
        out[2 * i]     = (accx + ds.x + cb3[0] + fb3[0]) * (1.f / 128.f);
        out[2 * i + 1] = (accy + ds.y + cb3[1] + fb3[1]) * (1.f / 128.f);
    }
}

// ---------------- launch ----------------------------------------------------
extern "C" void kernel_launch(void* const* d_in, const int* in_sizes, int n_in,
                              void* d_out, int out_size) {
    const float* pos  = (const float*)d_in[0];
    const float* feat = (const float*)d_in[1];
    const int*   ei   = (const int*)d_in[2];
    const int*   ej   = (const int*)d_in[3];
    const float* cw0 = (const float*)d_in[4];
    const float* cb0 = (const float*)d_in[5];
    const float* fw0 = (const float*)d_in[6];
    const float* fb0 = (const float*)d_in[7];
    const float* cw1 = (const float*)d_in[8];
    const float* cb1 = (const float*)d_in[9];
    const float* fw1 = (const float*)d_in[10];
    const float* fb1 = (const float*)d_in[11];
    const float* cw2 = (const float*)d_in[12];
    const float* cb2 = (const float*)d_in[13];
    const float* fw2 = (const float*)d_in[14];
    const float* fb2 = (const float*)d_in[15];
    const float* cw3 = (const float*)d_in[16];
    const float* cb3 = (const float*)d_in[17];
    const float* fw3 = (const float*)d_in[18];
    const float* fb3 = (const float*)d_in[19];
    float* out = (float*)d_out;
    int E = in_sizes[2];

    cudaFuncSetAttribute(gemmA_kernel,
                         cudaFuncAttributeMaxDynamicSharedMemorySize, SMEMA);
    cudaFuncSetAttribute(gemmP_kernel,
                         cudaFuncAttributeMaxDynamicSharedMemorySize, PSMEM);

    __half* w1; cudaGetSymbolAddress((void**)&w1, g_wc1);
    __half* w2; cudaGetSymbolAddress((void**)&w2, g_wc2);
    __half* w3; cudaGetSymbolAddress((void**)&w3, g_wc3);
    float* b1;  cudaGetSymbolAddress((void**)&b1, g_bias1);
    float* b2;  cudaGetSymbolAddress((void**)&b2, g_bias2);

    // all weight packing + cnt zero in one launch
    packAll_kernel<<<(PACK_TOT + 255) / 256, 256>>>(
        cw0, fw0, cb0, fb0, cw1, fw1, cb1, fb1,
        cw2, fw2, cb2, fb2, cw3, fw3);

    // edge counting sort (single atomic pass; scan does local-scan once)
    hist_kernel<<<(E + 255) / 256, 256>>>(ei, E);
    scan1_kernel<<<SCAN_B, 1024>>>();
    scan2_kernel<<<1, 64>>>();
    scan3_kernel<<<SCAN_B, 1024>>>();
    scatter_kernel<<<(E + 255) / 256, 256>>>(pos, ei, ej, E);

    // layer 0 (moment formulation)
    mom0_kernel<<<NN / 8, 256>>>(feat);
    gemmA_kernel<<<391, 256, SMEMA>>>();

    // layer 1
    gemmP_kernel<<<dim3(391, 3), 256, PSMEM>>>(w1, NPAD, 11, 33, YS1);
    gather64_kernel<false, true><<<(NN * 32 + 255) / 256, 256>>>(b1);

    // layer 2 (residual = g_resH)
    gemmP_kernel<<<dim3(391, 3), 256, PSMEM>>>(w2, NPAD, 11, 33, YS1);
    gather64_kernel<true, false><<<(NN * 32 + 255) / 256, 256>>>(b2);

    // layer 3
    gemmP_kernel<<<dim3(391, 2), 256, PSMEM>>>(w3, 256, 1, 2, YS3);
    gatherF_kernel<<<(NN * 32 + 255) / 256, 256>>>(cb3, fb3, out);
}